// round 16
// baseline (speedup 1.0000x reference)
#include <cuda_runtime.h>
#include <cuda_bf16.h>
#include <math.h>
#include <stdint.h>

#define NB 48
#define NC 3
#define HH 256
#define WW 256
#define HP (HH + 10)              // padded rows in intermediate (5 top, 5 bot)
#define NIMG (NB * NC)            // 144

#define K1_BLOCKS (NIMG * 64)     // 4 rows x 64 quads per 256-thr block
#define K2_BLOCKS (NIMG * 32)     // 8 rows x 256 cols per 256-thr block

#define C1S 1e-4f
#define C2S 9e-4f

// 1D Gaussian (k=11, sigma=1.5) — compile-time constants -> FFMA-imm.
__device__ static constexpr float GK[11] = {
    0.00102840f, 0.00759880f, 0.03600060f, 0.10936270f, 0.21300441f,
    0.26601031f,
    0.21300441f, 0.10936270f, 0.03600060f, 0.00759880f, 0.00102840f
};

// Intermediate: 2x bf16x2 per px, 5 zero pad rows top+bottom per image.
// Pads never written (zero-initialized device global) -> no row guards in vconv.
__device__ uint2 g_h[(size_t)NIMG * HP * WW];   // ~78 MB
__device__ float g_partA[K1_BLOCKS];
__device__ float g_partB[K2_BLOCKS];

// ---------------------------------------------------------------------------
// Kernel 1: horizontal 11-tap conv of the 4 moment fields + weighted L1.
// Prologue computes this block's polygon data (3 bboxes + 4 rows x 24 edge
// crossings) directly into smem — no edge kernel, no g_edge/g_bbox globals.
// One thread = 4 output cols of one row. Interior quads load unconditionally.
// ---------------------------------------------------------------------------
__global__ void __launch_bounds__(256, 2)
hconv_kernel(const float* __restrict__ pred, const float* __restrict__ targ,
             const float* __restrict__ lm)
{
    __shared__ float s_r[8];
    __shared__ float lx[24], ly[24];
    __shared__ float sbx0[4], sbx1[4], sby0[4], sby1[4];  // [3] used, pad 4
    __shared__ float s_sx[4][24];

    const int tid = threadIdx.x;
    const int warp = tid >> 5, lane = tid & 31;
    const int quad = tid & 63;                 // 64 col-quads
    const int img = blockIdx.x >> 6;
    const int r0 = (blockIdx.x & 63) << 2;
    const int rl = tid >> 6;                   // row-in-block 0..3
    const int row = r0 + rl;
    const int n = img / NC;

    // ---- prologue: landmarks -> bboxes -> crossing table (smem only) ----
    if (tid < 24) {
        lx[tid] = lm[(n * 68 + 36 + tid) * 2 + 0];
        ly[tid] = lm[(n * 68 + 36 + tid) * 2 + 1];
    }
    __syncthreads();
    if (tid < 3) {
        const int b = tid * 6;
        const int np = (tid == 2) ? 12 : 6;
        float mnx = lx[b], mxx = lx[b], mny = ly[b], mxy = ly[b];
        for (int i = 1; i < np; i++) {
            mnx = fminf(mnx, lx[b + i]); mxx = fmaxf(mxx, lx[b + i]);
            mny = fminf(mny, ly[b + i]); mxy = fmaxf(mxy, ly[b + i]);
        }
        float fx0 = floorf(mnx), fx1 = floorf(mxx);
        float fy0 = floorf(mny), fy1 = floorf(mxy);
        const bool valid = (fx0 >= 0.f && fy0 >= 0.f &&
                            fx1 < (float)WW && fy1 < (float)HH);
        if (!valid) { fx0 = 1e30f; fx1 = -1e30f; fy0 = 1e30f; fy1 = -1e30f; }
        sbx0[tid] = fx0; sbx1[tid] = fx1; sby0[tid] = fy0; sby1[tid] = fy1;
    }
    __syncthreads();
    if (tid < 96) {
        const int rr = tid / 24;               // local row
        const int e = tid - rr * 24;
        const int p3 = (e < 6) ? 0 : (e < 12) ? 1 : 2;
        const int base = p3 * 6;
        const int np = (p3 == 2) ? 12 : 6;
        const float Y = (float)(r0 + rr);
        const float x1 = lx[e], y1 = ly[e];
        const int e2 = base + ((e - base + 1) % np);
        const float x2 = lx[e2], y2 = ly[e2];
        const bool strad = (y1 > Y) != (y2 > Y);
        const bool rowok = (Y >= sby0[p3]) && (Y < sby1[p3]);
        const float xi = (x2 - x1) * (Y - y1) / (y2 - y1 + 1e-6f) + x1;
        s_sx[rr][e] = (strad && rowok) ? xi : -1e30f;
    }
    __syncthreads();

    const float* __restrict__ P = pred + (size_t)img * (HH * WW) + row * WW;
    const float* __restrict__ T = targ + (size_t)img * (HH * WW) + row * WW;

    // load window: cols [4q-8, 4q+12) — 5 aligned float4 pairs
    const int wb = (quad << 2) - 8;
    float p[20], t[20];
    if (quad >= 2 && quad <= 61) {
        #pragma unroll
        for (int m = 0; m < 5; m++) {
            const float4 vp = *(const float4*)(P + wb + 4 * m);
            const float4 vt = *(const float4*)(T + wb + 4 * m);
            p[4*m+0] = vp.x; p[4*m+1] = vp.y; p[4*m+2] = vp.z; p[4*m+3] = vp.w;
            t[4*m+0] = vt.x; t[4*m+1] = vt.y; t[4*m+2] = vt.z; t[4*m+3] = vt.w;
        }
    } else {
        #pragma unroll
        for (int m = 0; m < 5; m++) {
            const int gc = wb + 4 * m;
            float4 vp = make_float4(0.f, 0.f, 0.f, 0.f);
            float4 vt = make_float4(0.f, 0.f, 0.f, 0.f);
            if ((unsigned)gc < (unsigned)WW) {
                vp = *(const float4*)(P + gc);
                vt = *(const float4*)(T + gc);
            }
            p[4*m+0] = vp.x; p[4*m+1] = vp.y; p[4*m+2] = vp.z; p[4*m+3] = vp.w;
            t[4*m+0] = vt.x; t[4*m+1] = vt.y; t[4*m+2] = vt.z; t[4*m+3] = vt.w;
        }
    }

    float s2[14], pt[14];
    #pragma unroll
    for (int u = 0; u < 14; u++) {
        s2[u] = fmaf(p[u+3], p[u+3], t[u+3] * t[u+3]);   // p^2 + t^2
        pt[u] = p[u+3] * t[u+3];
    }

    uint2* __restrict__ Hout =
        g_h + (size_t)img * (HP * WW) + (row + 5) * WW;
    unsigned ow[8];
    #pragma unroll
    for (int k = 0; k < 4; k++) {
        float a = 0.f, b = 0.f, c = 0.f, e = 0.f;
        #pragma unroll
        for (int j = 0; j < 11; j++) {
            const float g = GK[j];
            a += g * p[k + j + 3];
            b += g * t[k + j + 3];
            c += g * s2[k + j];
            e += g * pt[k + j];
        }
        __nv_bfloat162 hab = __floats2bfloat162_rn(a, b);
        __nv_bfloat162 hce = __floats2bfloat162_rn(c, e);
        ow[2*k]   = reinterpret_cast<unsigned&>(hab);
        ow[2*k+1] = reinterpret_cast<unsigned&>(hce);
    }
    uint4* dst = (uint4*)(Hout + (quad << 2));
    dst[0] = make_uint4(ow[0], ow[1], ow[2], ow[3]);
    dst[1] = make_uint4(ow[4], ow[5], ow[6], ow[7]);

    // ---- weighted L1 for these 4 pixels ----
    float acc = 0.f;
    const float bxa0 = sbx0[0], bxa1 = sbx1[0];
    const float bxb0 = sbx0[1], bxb1 = sbx1[1];
    const float bxc0 = sbx0[2], bxc1 = sbx1[2];
    const float cf = (float)(quad << 2);
    const float cl = cf + 3.f;
    const bool tin = (bxa0 <= cl && bxa1 > cf) ||
                     (bxb0 <= cl && bxb1 > cf) ||
                     (bxc0 <= cl && bxc1 > cf);
    if (__any_sync(0xffffffffu, tin)) {
        const float* sx = s_sx[rl];
        #pragma unroll
        for (int k = 0; k < 4; k++) {
            const float ad = fabsf(p[8 + k] - t[8 + k]);
            const float X = cf + (float)k;
            float w = 1.f;
            if (X >= bxa0 && X < bxa1) {
                int par = (X < sx[0]) ^ (X < sx[1]) ^ (X < sx[2]) ^
                          (X < sx[3]) ^ (X < sx[4]) ^ (X < sx[5]);
                if (par) w += 3.f;
            }
            if (X >= bxb0 && X < bxb1) {
                int par = (X < sx[6]) ^ (X < sx[7]) ^ (X < sx[8]) ^
                          (X < sx[9]) ^ (X < sx[10]) ^ (X < sx[11]);
                if (par) w += 3.f;
            }
            if (X >= bxc0 && X < bxc1) {
                int par = (X < sx[12]) ^ (X < sx[13]) ^ (X < sx[14]) ^
                          (X < sx[15]) ^ (X < sx[16]) ^ (X < sx[17]) ^
                          (X < sx[18]) ^ (X < sx[19]) ^ (X < sx[20]) ^
                          (X < sx[21]) ^ (X < sx[22]) ^ (X < sx[23]);
                if (par) w += 2.f;
            }
            acc += (10.f + 5.f * w) * ad;
        }
    } else {
        #pragma unroll
        for (int k = 0; k < 4; k++)
            acc += 15.f * fabsf(p[8 + k] - t[8 + k]);
    }

    // deterministic block reduce
    #pragma unroll
    for (int o = 16; o > 0; o >>= 1)
        acc += __shfl_down_sync(0xffffffffu, acc, o);
    if (lane == 0) s_r[warp] = acc;
    __syncthreads();
    if (warp == 0) {
        float v = (lane < 8) ? s_r[lane] : 0.f;
        #pragma unroll
        for (int o = 4; o > 0; o >>= 1)
            v += __shfl_down_sync(0xffffffffu, v, o);
        if (lane == 0) g_partA[blockIdx.x] = v;
    }
}

// ---------------------------------------------------------------------------
// Kernel 2: vertical 11-tap conv (8 rows / thread) + SSIM. No row guards
// (zero-padded intermediate).
// ---------------------------------------------------------------------------
__global__ void __launch_bounds__(256)
vconv_kernel()
{
    __shared__ float s_r[8];

    const int c = threadIdx.x;
    const int warp = c >> 5, lane = c & 31;
    const int img = blockIdx.x >> 5;
    const int rg = blockIdx.x & 31;            // 8-row group

    const uint2* __restrict__ H =
        g_h + (size_t)img * (HP * WW) + (rg << 3) * WW + c;

    float4 a0 = {0,0,0,0}, a1 = {0,0,0,0}, a2 = {0,0,0,0}, a3 = {0,0,0,0};
    float4 a4 = {0,0,0,0}, a5 = {0,0,0,0}, a6 = {0,0,0,0}, a7 = {0,0,0,0};

    #pragma unroll
    for (int rr = 0; rr < 18; rr++) {
        const uint2 u2 = H[rr * WW];
        const __nv_bfloat162 bab = reinterpret_cast<const __nv_bfloat162&>(u2.x);
        const __nv_bfloat162 bce = reinterpret_cast<const __nv_bfloat162&>(u2.y);
        const float2 fab = __bfloat1622float2(bab);
        const float2 fce = __bfloat1622float2(bce);
        const float4 v = make_float4(fab.x, fab.y, fce.x, fce.y);
        #pragma unroll
        for (int k = 0; k < 8; k++) {
            const int j = rr - k;
            if (j >= 0 && j < 11) {
                const float g = GK[j];
                float4* a = (k==0)?&a0:(k==1)?&a1:(k==2)?&a2:(k==3)?&a3:
                            (k==4)?&a4:(k==5)?&a5:(k==6)?&a6:&a7;
                a->x += g * v.x;
                a->y += g * v.y;
                a->z += g * v.z;
                a->w += g * v.w;
            }
        }
    }

    float sds = 0.f;
    #pragma unroll
    for (int k = 0; k < 8; k++) {
        const float4 a = (k==0)?a0:(k==1)?a1:(k==2)?a2:(k==3)?a3:
                         (k==4)?a4:(k==5)?a5:(k==6)?a6:a7;
        const float mx = a.x, my = a.y;
        const float mx2my2 = mx * mx + my * my;
        const float sxsy = a.z - mx2my2;       // sigma_x + sigma_y
        const float sxy = a.w - mx * my;       // sigma_xy
        const float num = (2.f * mx * my + C1S) * (2.f * sxy + C2S);
        const float den = (mx2my2 + C1S) * (sxsy + C2S) + 1e-8f;
        sds += (1.f - __fdividef(num, den));
    }
    float acc = 5.f * sds;                     // 10 * (1-ssim)/2

    #pragma unroll
    for (int o = 16; o > 0; o >>= 1)
        acc += __shfl_down_sync(0xffffffffu, acc, o);
    if (lane == 0) s_r[warp] = acc;
    __syncthreads();
    if (warp == 0) {
        float v = (lane < 8) ? s_r[lane] : 0.f;
        #pragma unroll
        for (int o = 4; o > 0; o >>= 1)
            v += __shfl_down_sync(0xffffffffu, v, o);
        if (lane == 0) g_partB[blockIdx.x] = v;
    }
}

// ---------------------------------------------------------------------------
// Final deterministic reduction: 8 rotating double accumulators.
// ---------------------------------------------------------------------------
__global__ void __launch_bounds__(256) reduce_kernel(float* __restrict__ out)
{
    __shared__ double sd[256];
    const int tid = threadIdx.x;
    double s[8] = {0, 0, 0, 0, 0, 0, 0, 0};
    {
        int j = 0;
        for (int i = tid; i < K1_BLOCKS; i += 256) {
            s[j] += (double)g_partA[i];
            j = (j + 1) & 7;
        }
        j = 0;
        for (int i = tid; i < K2_BLOCKS; i += 256) {
            s[j] += (double)g_partB[i];
            j = (j + 1) & 7;
        }
    }
    sd[tid] = ((s[0] + s[1]) + (s[2] + s[3])) + ((s[4] + s[5]) + (s[6] + s[7]));
    __syncthreads();
    for (int st = 128; st > 0; st >>= 1) {
        if (tid < st) sd[tid] += sd[tid + st];
        __syncthreads();
    }
    if (tid == 0) {
        out[0] = (float)(sd[0] / ((double)NB * (double)NC * (double)HH * (double)WW));
    }
}

extern "C" void kernel_launch(void* const* d_in, const int* in_sizes, int n_in,
                              void* d_out, int out_size)
{
    const float* pred = (const float*)d_in[0];
    const float* targ = (const float*)d_in[1];
    const float* lm   = (const float*)d_in[2];
    float* out = (float*)d_out;
    (void)in_sizes; (void)n_in; (void)out_size;

    hconv_kernel<<<K1_BLOCKS, 256>>>(pred, targ, lm);
    vconv_kernel<<<K2_BLOCKS, 256>>>();
    reduce_kernel<<<1, 256>>>(out);
}

// round 17
// speedup vs baseline: 1.1682x; 1.1682x over previous
#include <cuda_runtime.h>
#include <cuda_bf16.h>
#include <math.h>
#include <stdint.h>

#define NB 48
#define NC 3
#define HH 256
#define WW 256
#define HP (HH + 10)              // padded rows in intermediate (5 top, 5 bot)
#define NIMG (NB * NC)            // 144

#define K1_BLOCKS (NIMG * 64)     // 4 rows x 64 quads per 256-thr block
#define K2_BLOCKS (NIMG * 32)     // 8 rows x 256 cols per 256-thr block

#define C1S 1e-4f
#define C2S 9e-4f

// 1D Gaussian (k=11, sigma=1.5) — compile-time constants -> FFMA-imm.
__device__ static constexpr float GK[11] = {
    0.00102840f, 0.00759880f, 0.03600060f, 0.10936270f, 0.21300441f,
    0.26601031f,
    0.21300441f, 0.10936270f, 0.03600060f, 0.00759880f, 0.00102840f
};

__device__ float g_edge[NB * HH * 24];   // per-(n,row,edge) crossing-x
__device__ float g_bbox[NB * 8];         // per-n: bx0[3], bx1[3]
// Intermediate: 2x bf16x2 per px, 5 zero pad rows top+bottom per image.
// Pads never written (zero-initialized device global) -> no row guards in vconv.
__device__ uint2 g_h[(size_t)NIMG * HP * WW];   // ~78 MB
__device__ float g_partA[K1_BLOCKS];
__device__ float g_partB[K2_BLOCKS];

// ---------------------------------------------------------------------------
// Kernel A: per-(n,row,edge) crossing table + x-bboxes.
// Grid (NB, 8): each block handles 32 rows so the launch fills the chip.
// ---------------------------------------------------------------------------
__global__ void __launch_bounds__(256) edge_kernel(const float* __restrict__ lm)
{
    __shared__ float lx[24], ly[24];
    __shared__ float bx0[3], bx1[3], by0[3], by1[3];

    const int n = blockIdx.x;
    const int rb = blockIdx.y;               // row-group 0..7 (32 rows each)
    const int tid = threadIdx.x;

    if (tid < 24) {
        lx[tid] = lm[(n * 68 + 36 + tid) * 2 + 0];
        ly[tid] = lm[(n * 68 + 36 + tid) * 2 + 1];
    }
    __syncthreads();
    if (tid < 3) {
        const int b = tid * 6;
        const int np = (tid == 2) ? 12 : 6;
        float mnx = lx[b], mxx = lx[b], mny = ly[b], mxy = ly[b];
        for (int i = 1; i < np; i++) {
            mnx = fminf(mnx, lx[b + i]); mxx = fmaxf(mxx, lx[b + i]);
            mny = fminf(mny, ly[b + i]); mxy = fmaxf(mxy, ly[b + i]);
        }
        float fx0 = floorf(mnx), fx1 = floorf(mxx);
        float fy0 = floorf(mny), fy1 = floorf(mxy);
        const bool valid = (fx0 >= 0.f && fy0 >= 0.f &&
                            fx1 < (float)WW && fy1 < (float)HH);
        if (!valid) { fx0 = 1e30f; fx1 = -1e30f; fy0 = 1e30f; fy1 = -1e30f; }
        bx0[tid] = fx0; bx1[tid] = fx1; by0[tid] = fy0; by1[tid] = fy1;
        if (rb == 0) {
            g_bbox[n * 8 + tid]     = fx0;
            g_bbox[n * 8 + 4 + tid] = fx1;
        }
    }
    __syncthreads();

    // 32 rows x 24 edges = 768 items, 3 iterations of 256 threads
    const int ub = rb * 32 * 24;
    #pragma unroll
    for (int v = 0; v < 3; v++) {
        const int u = ub + v * 256 + tid;
        const int row = u / 24;
        const int e = u - row * 24;
        const int p3 = (e < 6) ? 0 : (e < 12) ? 1 : 2;
        const int base = p3 * 6;
        const int np = (p3 == 2) ? 12 : 6;
        const float Y = (float)row;
        const float x1 = lx[e], y1 = ly[e];
        const int e2 = base + ((e - base + 1) % np);
        const float x2 = lx[e2], y2 = ly[e2];
        const bool strad = (y1 > Y) != (y2 > Y);
        const bool rowok = (Y >= by0[p3]) && (Y < by1[p3]);
        const float xi = (x2 - x1) * (Y - y1) / (y2 - y1 + 1e-6f) + x1;
        g_edge[(size_t)n * HH * 24 + u] = (strad && rowok) ? xi : -1e30f;
    }
}

// ---------------------------------------------------------------------------
// Kernel 1: horizontal 11-tap conv of the 4 moment fields + weighted L1.
// One thread = 4 output cols of one row. Interior quads (2..61) take a
// fully unconditional load path. launch_bounds(256,5) caps regs at 51 to
// lift occupancy from 4 to 5 CTAs/SM.
// ---------------------------------------------------------------------------
__global__ void __launch_bounds__(256, 5)
hconv_kernel(const float* __restrict__ pred, const float* __restrict__ targ)
{
    __shared__ float s_r[8];

    const int tid = threadIdx.x;
    const int warp = tid >> 5, lane = tid & 31;
    const int quad = tid & 63;                 // 64 col-quads
    const int img = blockIdx.x >> 6;
    const int row = ((blockIdx.x & 63) << 2) + (tid >> 6);
    const int n = img / NC;

    const float* __restrict__ P = pred + (size_t)img * (HH * WW) + row * WW;
    const float* __restrict__ T = targ + (size_t)img * (HH * WW) + row * WW;

    // load window: cols [4q-8, 4q+12) — 5 aligned float4 pairs
    const int wb = (quad << 2) - 8;
    float p[20], t[20];
    if (quad >= 2 && quad <= 61) {
        #pragma unroll
        for (int m = 0; m < 5; m++) {
            const float4 vp = *(const float4*)(P + wb + 4 * m);
            const float4 vt = *(const float4*)(T + wb + 4 * m);
            p[4*m+0] = vp.x; p[4*m+1] = vp.y; p[4*m+2] = vp.z; p[4*m+3] = vp.w;
            t[4*m+0] = vt.x; t[4*m+1] = vt.y; t[4*m+2] = vt.z; t[4*m+3] = vt.w;
        }
    } else {
        #pragma unroll
        for (int m = 0; m < 5; m++) {
            const int gc = wb + 4 * m;
            float4 vp = make_float4(0.f, 0.f, 0.f, 0.f);
            float4 vt = make_float4(0.f, 0.f, 0.f, 0.f);
            if ((unsigned)gc < (unsigned)WW) {
                vp = *(const float4*)(P + gc);
                vt = *(const float4*)(T + gc);
            }
            p[4*m+0] = vp.x; p[4*m+1] = vp.y; p[4*m+2] = vp.z; p[4*m+3] = vp.w;
            t[4*m+0] = vt.x; t[4*m+1] = vt.y; t[4*m+2] = vt.z; t[4*m+3] = vt.w;
        }
    }

    float s2[14], pt[14];
    #pragma unroll
    for (int u = 0; u < 14; u++) {
        s2[u] = fmaf(p[u+3], p[u+3], t[u+3] * t[u+3]);   // p^2 + t^2
        pt[u] = p[u+3] * t[u+3];
    }

    uint2* __restrict__ Hout =
        g_h + (size_t)img * (HP * WW) + (row + 5) * WW;
    unsigned ow[8];
    #pragma unroll
    for (int k = 0; k < 4; k++) {
        float a = 0.f, b = 0.f, c = 0.f, e = 0.f;
        #pragma unroll
        for (int j = 0; j < 11; j++) {
            const float g = GK[j];
            a += g * p[k + j + 3];
            b += g * t[k + j + 3];
            c += g * s2[k + j];
            e += g * pt[k + j];
        }
        __nv_bfloat162 hab = __floats2bfloat162_rn(a, b);
        __nv_bfloat162 hce = __floats2bfloat162_rn(c, e);
        ow[2*k]   = reinterpret_cast<unsigned&>(hab);
        ow[2*k+1] = reinterpret_cast<unsigned&>(hce);
    }
    uint4* dst = (uint4*)(Hout + (quad << 2));
    dst[0] = make_uint4(ow[0], ow[1], ow[2], ow[3]);
    dst[1] = make_uint4(ow[4], ow[5], ow[6], ow[7]);

    // ---- weighted L1 for these 4 pixels ----
    float acc = 0.f;
    const float bxa0 = g_bbox[n * 8 + 0], bxa1 = g_bbox[n * 8 + 4];
    const float bxb0 = g_bbox[n * 8 + 1], bxb1 = g_bbox[n * 8 + 5];
    const float bxc0 = g_bbox[n * 8 + 2], bxc1 = g_bbox[n * 8 + 6];
    const float cf = (float)(quad << 2);
    const float cl = cf + 3.f;
    const bool tin = (bxa0 <= cl && bxa1 > cf) ||
                     (bxb0 <= cl && bxb1 > cf) ||
                     (bxc0 <= cl && bxc1 > cf);
    if (__any_sync(0xffffffffu, tin)) {
        float sx[24];
        const float* __restrict__ E = g_edge + ((size_t)n * HH + row) * 24;
        #pragma unroll
        for (int e2 = 0; e2 < 24; e2++) sx[e2] = E[e2];
        #pragma unroll
        for (int k = 0; k < 4; k++) {
            const float ad = fabsf(p[8 + k] - t[8 + k]);
            const float X = cf + (float)k;
            float w = 1.f;
            if (X >= bxa0 && X < bxa1) {
                int par = (X < sx[0]) ^ (X < sx[1]) ^ (X < sx[2]) ^
                          (X < sx[3]) ^ (X < sx[4]) ^ (X < sx[5]);
                if (par) w += 3.f;
            }
            if (X >= bxb0 && X < bxb1) {
                int par = (X < sx[6]) ^ (X < sx[7]) ^ (X < sx[8]) ^
                          (X < sx[9]) ^ (X < sx[10]) ^ (X < sx[11]);
                if (par) w += 3.f;
            }
            if (X >= bxc0 && X < bxc1) {
                int par = (X < sx[12]) ^ (X < sx[13]) ^ (X < sx[14]) ^
                          (X < sx[15]) ^ (X < sx[16]) ^ (X < sx[17]) ^
                          (X < sx[18]) ^ (X < sx[19]) ^ (X < sx[20]) ^
                          (X < sx[21]) ^ (X < sx[22]) ^ (X < sx[23]);
                if (par) w += 2.f;
            }
            acc += (10.f + 5.f * w) * ad;
        }
    } else {
        #pragma unroll
        for (int k = 0; k < 4; k++)
            acc += 15.f * fabsf(p[8 + k] - t[8 + k]);
    }

    // deterministic block reduce
    #pragma unroll
    for (int o = 16; o > 0; o >>= 1)
        acc += __shfl_down_sync(0xffffffffu, acc, o);
    if (lane == 0) s_r[warp] = acc;
    __syncthreads();
    if (warp == 0) {
        float v = (lane < 8) ? s_r[lane] : 0.f;
        #pragma unroll
        for (int o = 4; o > 0; o >>= 1)
            v += __shfl_down_sync(0xffffffffu, v, o);
        if (lane == 0) g_partA[blockIdx.x] = v;
    }
}

// ---------------------------------------------------------------------------
// Kernel 2: vertical 11-tap conv (8 rows / thread) + SSIM. No row guards
// (zero-padded intermediate).
// ---------------------------------------------------------------------------
__global__ void __launch_bounds__(256)
vconv_kernel()
{
    __shared__ float s_r[8];

    const int c = threadIdx.x;
    const int warp = c >> 5, lane = c & 31;
    const int img = blockIdx.x >> 5;
    const int rg = blockIdx.x & 31;            // 8-row group

    const uint2* __restrict__ H =
        g_h + (size_t)img * (HP * WW) + (rg << 3) * WW + c;

    float4 a0 = {0,0,0,0}, a1 = {0,0,0,0}, a2 = {0,0,0,0}, a3 = {0,0,0,0};
    float4 a4 = {0,0,0,0}, a5 = {0,0,0,0}, a6 = {0,0,0,0}, a7 = {0,0,0,0};

    #pragma unroll
    for (int rr = 0; rr < 18; rr++) {
        const uint2 u2 = H[rr * WW];
        const __nv_bfloat162 bab = reinterpret_cast<const __nv_bfloat162&>(u2.x);
        const __nv_bfloat162 bce = reinterpret_cast<const __nv_bfloat162&>(u2.y);
        const float2 fab = __bfloat1622float2(bab);
        const float2 fce = __bfloat1622float2(bce);
        const float4 v = make_float4(fab.x, fab.y, fce.x, fce.y);
        #pragma unroll
        for (int k = 0; k < 8; k++) {
            const int j = rr - k;
            if (j >= 0 && j < 11) {
                const float g = GK[j];
                float4* a = (k==0)?&a0:(k==1)?&a1:(k==2)?&a2:(k==3)?&a3:
                            (k==4)?&a4:(k==5)?&a5:(k==6)?&a6:&a7;
                a->x += g * v.x;
                a->y += g * v.y;
                a->z += g * v.z;
                a->w += g * v.w;
            }
        }
    }

    float sds = 0.f;
    #pragma unroll
    for (int k = 0; k < 8; k++) {
        const float4 a = (k==0)?a0:(k==1)?a1:(k==2)?a2:(k==3)?a3:
                         (k==4)?a4:(k==5)?a5:(k==6)?a6:a7;
        const float mx = a.x, my = a.y;
        const float mx2my2 = mx * mx + my * my;
        const float sxsy = a.z - mx2my2;       // sigma_x + sigma_y
        const float sxy = a.w - mx * my;       // sigma_xy
        const float num = (2.f * mx * my + C1S) * (2.f * sxy + C2S);
        const float den = (mx2my2 + C1S) * (sxsy + C2S) + 1e-8f;
        sds += (1.f - __fdividef(num, den));
    }
    float acc = 5.f * sds;                     // 10 * (1-ssim)/2

    #pragma unroll
    for (int o = 16; o > 0; o >>= 1)
        acc += __shfl_down_sync(0xffffffffu, acc, o);
    if (lane == 0) s_r[warp] = acc;
    __syncthreads();
    if (warp == 0) {
        float v = (lane < 8) ? s_r[lane] : 0.f;
        #pragma unroll
        for (int o = 4; o > 0; o >>= 1)
            v += __shfl_down_sync(0xffffffffu, v, o);
        if (lane == 0) g_partB[blockIdx.x] = v;
    }
}

// ---------------------------------------------------------------------------
// Final deterministic reduction: 8 rotating double accumulators.
// ---------------------------------------------------------------------------
__global__ void __launch_bounds__(256) reduce_kernel(float* __restrict__ out)
{
    __shared__ double sd[256];
    const int tid = threadIdx.x;
    double s[8] = {0, 0, 0, 0, 0, 0, 0, 0};
    {
        int j = 0;
        for (int i = tid; i < K1_BLOCKS; i += 256) {
            s[j] += (double)g_partA[i];
            j = (j + 1) & 7;
        }
        j = 0;
        for (int i = tid; i < K2_BLOCKS; i += 256) {
            s[j] += (double)g_partB[i];
            j = (j + 1) & 7;
        }
    }
    sd[tid] = ((s[0] + s[1]) + (s[2] + s[3])) + ((s[4] + s[5]) + (s[6] + s[7]));
    __syncthreads();
    for (int st = 128; st > 0; st >>= 1) {
        if (tid < st) sd[tid] += sd[tid + st];
        __syncthreads();
    }
    if (tid == 0) {
        out[0] = (float)(sd[0] / ((double)NB * (double)NC * (double)HH * (double)WW));
    }
}

extern "C" void kernel_launch(void* const* d_in, const int* in_sizes, int n_in,
                              void* d_out, int out_size)
{
    const float* pred = (const float*)d_in[0];
    const float* targ = (const float*)d_in[1];
    const float* lm   = (const float*)d_in[2];
    float* out = (float*)d_out;
    (void)in_sizes; (void)n_in; (void)out_size;

    edge_kernel<<<dim3(NB, 8), 256>>>(lm);
    hconv_kernel<<<K1_BLOCKS, 256>>>(pred, targ);
    vconv_kernel<<<K2_BLOCKS, 256>>>();
    reduce_kernel<<<1, 256>>>(out);
}